// round 8
// baseline (speedup 1.0000x reference)
#include <cuda_runtime.h>
#include <cstdint>

// Problem constants: x is (16384, 2048) fp32, angles (2048,) fp32, out (16384, 2048) fp32.
constexpr int NN = 2048;   // row length n
constexpr int T  = 256;    // threads per block
constexpr int E  = 8;      // elements per thread (T*E == NN)
constexpr int R  = 8;      // rows per block (4 pairs, software-pipelined)
constexpr int PAIRS = R / 2;
constexpr int PAIR_BYTES = 2 * NN * (int)sizeof(float);   // 16 KB per bulk copy

// Precomputed tables (device globals: no dynamic allocation allowed).
__device__ __align__(16) float g_c[NN];
__device__ __align__(16) float g_s[NN];
// Row-independent scan weights (P-side of the affine scan):
__device__ float g_W5[5][T];   // warp suffix-scan jump weights (prod_{i<d} P_{t+i}, 0 past warp end)
__device__ float g_Pe[T];      // warp-exclusive product (lanes > lid, same warp)
__device__ float g_PfA[T];     // block-exclusive product (threads > t)
__device__ float g_Pw[8];      // per-warp total products

// ---------------- async-copy / mbarrier helpers ----------------
__device__ __forceinline__ uint32_t smem_u32(const void* p) {
    return (uint32_t)__cvta_generic_to_shared(p);
}
__device__ __forceinline__ void mbar_init(uint32_t a) {
    asm volatile("mbarrier.init.shared.b64 [%0], 1;" :: "r"(a) : "memory");
}
__device__ __forceinline__ void mbar_expect(uint32_t a, uint32_t bytes) {
    asm volatile("mbarrier.arrive.expect_tx.shared.b64 _, [%0], %1;"
                 :: "r"(a), "r"(bytes) : "memory");
}
__device__ __forceinline__ void bulk_cp(uint32_t dst, const void* src,
                                        uint32_t bytes, uint32_t mbar) {
    asm volatile("cp.async.bulk.shared::cta.global.mbarrier::complete_tx::bytes "
                 "[%0], [%1], %2, [%3];"
                 :: "r"(dst), "l"(src), "r"(bytes), "r"(mbar) : "memory");
}
__device__ __forceinline__ void mbar_wait(uint32_t a, uint32_t ph) {
    uint32_t done;
    asm volatile("{\n\t.reg .pred p;\n\t"
                 "mbarrier.try_wait.parity.acquire.cta.shared::cta.b64 p, [%1], %2;\n\t"
                 "selp.b32 %0, 1, 0, p;\n\t}"
                 : "=r"(done) : "r"(a), "r"(ph) : "memory");
    while (!done) {
        asm volatile("{\n\t.reg .pred p;\n\t"
                     "mbarrier.try_wait.parity.acquire.cta.shared::cta.b64 p, [%1], %2, 0x989680;\n\t"
                     "selp.b32 %0, 1, 0, p;\n\t}"
                     : "=r"(done) : "r"(a), "r"(ph) : "memory");
    }
}

// Fused prep, one block: sincos for all angles + all P-side scan constants.
__global__ void prep_kernel(const float* __restrict__ ang) {
    __shared__ float Slev[T];
    __shared__ float spw[8];
    const int t = threadIdx.x, lid = t & 31, w = t >> 5, lo = t * E;

    float ssl[E];
#pragma unroll
    for (int m = 0; m < E; ++m) {
        float s, c;
        sincosf(ang[lo + m], &s, &c);
        g_c[lo + m] = c;
        g_s[lo + m] = s;
        ssl[m] = s;
    }

    float P = 1.f;
#pragma unroll
    for (int m = E - 1; m >= 0; --m) {
        if (lo + m == NN - 1) continue;       // k = N-1 is the seed, not a scan step
        P *= -ssl[m];
    }

    // W levels by doubling: S_{2h}[t] = S_h[t] * S_h[t+h]   (0 past warp end)
    float S = P;
    g_W5[0][t] = (lid + 1 < 32) ? S : 0.f;
    for (int di = 1; di < 5; ++di) {
        const int d = 1 << di, half = d >> 1;
        __syncthreads();
        Slev[t] = S;
        __syncthreads();
        float part = (lid + half < 32) ? Slev[t + half] : 0.f;
        S *= part;
        g_W5[di][t] = (lid + d < 32) ? S : 0.f;
    }

    // warp inclusive suffix scan of P (prod over lanes >= lid)
    float Pscan = P;
#pragma unroll
    for (int d = 1; d < 32; d <<= 1) {
        float tmp = __shfl_down_sync(0xffffffffu, Pscan, d);
        if (lid + d < 32) Pscan *= tmp;
    }
    float Pe = __shfl_down_sync(0xffffffffu, Pscan, 1);
    if (lid == 31) Pe = 1.f;
    g_Pe[t] = Pe;
    if (lid == 0) spw[w] = Pscan;             // warp total
    __syncthreads();

    float Pf = Pe;
    for (int w2 = w + 1; w2 < 8; ++w2) Pf *= spw[w2];
    g_PfA[t] = Pf;
    if (t < 8) g_Pw[t] = spw[t];
}

// y_row = G_0 (G_1 (... (G_{N-1} x_row))). First-order affine recurrence on the
// carry; Q-only weighted warp suffix scan (P-side precomputed). Rows stream
// through double-buffered smem via cp.async.bulk: the DMA engine fills the
// next pair while the current pair computes — prefetch with zero register cost.
__global__ void __launch_bounds__(T, 4) givens_kernel(const float* __restrict__ x,
                                                      float* __restrict__ y) {
    __shared__ __align__(16) float buf[2][2 * NN];      // two 16 KB pair-buffers
    __shared__ __align__(16) float wtQ[2][2][8];        // [pair parity][row][warp]
    __shared__ __align__(8) unsigned long long mbar_s[2];

    const int t   = threadIdx.x;
    const int lid = t & 31;
    const int w   = t >> 5;
    const int lo  = t * E;
    const long base = (long)blockIdx.x * R;

    const uint32_t mb0 = smem_u32(&mbar_s[0]);
    const uint32_t mb1 = smem_u32(&mbar_s[1]);

    if (t == 0) { mbar_init(mb0); mbar_init(mb1); }
    __syncthreads();
    if (t == 0) {
        mbar_expect(mb0, PAIR_BYTES);
        bulk_cp(smem_u32(buf[0]), x + base * NN, PAIR_BYTES, mb0);
        mbar_expect(mb1, PAIR_BYTES);
        bulk_cp(smem_u32(buf[1]), x + (base + 2) * NN, PAIR_BYTES, mb1);
    }

    // ---- per-block constants into registers (overlaps with first DMA) ----
    float cc[E], ss[E];
    {
        float4 c0 = reinterpret_cast<const float4*>(g_c + lo)[0];
        float4 c1 = reinterpret_cast<const float4*>(g_c + lo)[1];
        cc[0] = c0.x; cc[1] = c0.y; cc[2] = c0.z; cc[3] = c0.w;
        cc[4] = c1.x; cc[5] = c1.y; cc[6] = c1.z; cc[7] = c1.w;
        float4 s0 = reinterpret_cast<const float4*>(g_s + lo)[0];
        float4 s1 = reinterpret_cast<const float4*>(g_s + lo)[1];
        ss[0] = s0.x; ss[1] = s0.y; ss[2] = s0.z; ss[3] = s0.w;
        ss[4] = s1.x; ss[5] = s1.y; ss[6] = s1.z; ss[7] = s1.w;
    }
    float W[5];
#pragma unroll
    for (int di = 0; di < 5; ++di) W[di] = g_W5[di][t];
    const float Pe = g_Pe[t];
    const float Pf = g_PfA[t];
    const float pw1 = g_Pw[1], pw2 = g_Pw[2], pw3 = g_Pw[3],
                pw4 = g_Pw[4], pw5 = g_Pw[5], pw6 = g_Pw[6];
    const float cN = g_c[NN - 1];
    const float sN = g_s[NN - 1];

    const bool warp_head = (lid == 0) && (w > 0);
    float cprev = 0.f, sprev = 0.f;
    if (warp_head) { cprev = g_c[lo - 1]; sprev = g_s[lo - 1]; }

#pragma unroll 1
    for (int p = 0; p < PAIRS; ++p) {
        const int bi = p & 1;
        const uint32_t mb = bi ? mb1 : mb0;
        mbar_wait(mb, (p >> 1) & 1);

        const float* bA = buf[bi];
        const float* bB = buf[bi] + NN;

        float xa[E], xb[E];
        {
            float4 a0 = reinterpret_cast<const float4*>(bA + lo)[0];
            float4 a1 = reinterpret_cast<const float4*>(bA + lo)[1];
            float4 b0 = reinterpret_cast<const float4*>(bB + lo)[0];
            float4 b1 = reinterpret_cast<const float4*>(bB + lo)[1];
            xa[0] = a0.x; xa[1] = a0.y; xa[2] = a0.z; xa[3] = a0.w;
            xa[4] = a1.x; xa[5] = a1.y; xa[6] = a1.z; xa[7] = a1.w;
            xb[0] = b0.x; xb[1] = b0.y; xb[2] = b0.z; xb[3] = b0.w;
            xb[4] = b1.x; xb[5] = b1.y; xb[6] = b1.z; xb[7] = b1.w;
        }
        // Boundary values straight from the smem tile (no exchange machinery):
        const float x0A = bA[0], xn1A = bA[NN - 1];
        const float x0B = bB[0], xn1B = bB[NN - 1];
        const float xpvA = warp_head ? bA[lo - 1] : 0.f;
        const float xpvB = warp_head ? bB[lo - 1] : 0.f;

        const float seedA = fmaf(cN, xn1A, -sN * x0A);   // prev_{N-1}
        const float seedB = fmaf(cN, xn1B, -sN * x0B);
        if (t == 0) {
            xa[0] = fmaf(sN, xn1A, cN * x0A);            // X_0 fix (thread 0's Q is unused)
            xb[0] = fmaf(sN, xn1B, cN * x0B);
        }

        // ---- Q composition for both rows (independent chains) ----
        float QA = 0.f, QB = 0.f;
#pragma unroll
        for (int m = E - 1; m >= 0; --m) {
            if (lo + m == NN - 1) continue;              // seed step
            QA = fmaf(-ss[m], QA, cc[m] * xa[m]);
            QB = fmaf(-ss[m], QB, cc[m] * xb[m]);
        }

        // ---- Q-only weighted warp suffix scan, both rows interleaved ----
#pragma unroll
        for (int di = 0, d = 1; di < 5; ++di, d <<= 1) {
            float qa2 = __shfl_down_sync(0xffffffffu, QA, d);
            float qb2 = __shfl_down_sync(0xffffffffu, QB, d);
            QA = fmaf(W[di], qa2, QA);
            QB = fmaf(W[di], qb2, QB);
        }
        float QeA = __shfl_down_sync(0xffffffffu, QA, 1);
        float QeB = __shfl_down_sync(0xffffffffu, QB, 1);
        if (lid == 31) { QeA = 0.f; QeB = 0.f; }

        if (lid == 0) { wtQ[bi][0][w] = QA; wtQ[bi][1][w] = QB; }
        __syncthreads();            // one barrier per pair; also proves buffer drained

        // ---- reissue this buffer for pair p+2 (DMA overlaps the rest) ----
        if (t == 0 && p + 2 < PAIRS) {
            mbar_expect(mb, PAIR_BYTES);
            bulk_cp(smem_u32(buf[bi]), x + (base + 2 * (p + 2)) * NN, PAIR_BYTES, mb);
        }

        // ---- cross-warp Horner over later warps, both rows ----
        float4 qa0 = *reinterpret_cast<const float4*>(&wtQ[bi][0][0]);
        float4 qa1 = *reinterpret_cast<const float4*>(&wtQ[bi][0][4]);
        float4 qb0 = *reinterpret_cast<const float4*>(&wtQ[bi][1][0]);
        float4 qb1 = *reinterpret_cast<const float4*>(&wtQ[bi][1][4]);
        float QpA = 0.f, QpB = 0.f;
        if (w < 7) { QpA = qa1.w;                 QpB = qb1.w; }
        if (w < 6) { QpA = fmaf(pw6, QpA, qa1.z); QpB = fmaf(pw6, QpB, qb1.z); }
        if (w < 5) { QpA = fmaf(pw5, QpA, qa1.y); QpB = fmaf(pw5, QpB, qb1.y); }
        if (w < 4) { QpA = fmaf(pw4, QpA, qa1.x); QpB = fmaf(pw4, QpB, qb1.x); }
        if (w < 3) { QpA = fmaf(pw3, QpA, qa0.w); QpB = fmaf(pw3, QpB, qb0.w); }
        if (w < 2) { QpA = fmaf(pw2, QpA, qa0.z); QpB = fmaf(pw2, QpB, qb0.z); }
        if (w < 1) { QpA = fmaf(pw1, QpA, qa0.y); QpB = fmaf(pw1, QpB, qb0.y); }

        float prevA = fmaf(Pf, seedA, fmaf(Pe, QpA, QeA));
        float prevB = fmaf(Pf, seedB, fmaf(Pe, QpB, QeB));

        // ---- replay in place, both rows; ends with prev = prev_lo ----
#pragma unroll
        for (int m = E - 1; m >= 0; --m) {
            if (lo + m == NN - 1) { xa[m] = 0.f; xb[m] = 0.f; continue; }
            const float xmA = xa[m], xmB = xb[m];
            xa[m] = fmaf(ss[m], xmA, cc[m] * prevA);
            prevA = fmaf(-ss[m], prevA, cc[m] * xmA);
            xb[m] = fmaf(ss[m], xmB, cc[m] * prevB);
            prevB = fmaf(-ss[m], prevB, cc[m] * xmB);
        }

        // out[lo]: lanes 1-31 take previous lane's xv[7]; warp heads recompute;
        // thread 0 has it as prev_0.
        float carryA = __shfl_up_sync(0xffffffffu, xa[E - 1], 1);
        float carryB = __shfl_up_sync(0xffffffffu, xb[E - 1], 1);
        if (t == 0) {
            carryA = prevA; carryB = prevB;
        } else if (warp_head) {
            carryA = fmaf(sprev, xpvA, cprev * prevA);
            carryB = fmaf(sprev, xpvB, cprev * prevB);
        }

        float* yrA = y + (base + 2 * p) * NN;
        float* yrB = yrA + NN;
        float4 oa0, oa1, ob0, ob1;
        oa0.x = carryA; oa0.y = xa[0]; oa0.z = xa[1]; oa0.w = xa[2];
        oa1.x = xa[3];  oa1.y = xa[4]; oa1.z = xa[5]; oa1.w = xa[6];
        ob0.x = carryB; ob0.y = xb[0]; ob0.z = xb[1]; ob0.w = xb[2];
        ob1.x = xb[3];  ob1.y = xb[4]; ob1.z = xb[5]; ob1.w = xb[6];
        __stcs(reinterpret_cast<float4*>(yrA + lo), oa0);
        __stcs(reinterpret_cast<float4*>(yrA + lo) + 1, oa1);
        __stcs(reinterpret_cast<float4*>(yrB + lo), ob0);
        __stcs(reinterpret_cast<float4*>(yrB + lo) + 1, ob1);
    }
}

// Fallback for any remainder rows (rows % R != 0): one row per block, direct loads.
// Not triggered for the fixed B=16384, but kept for generality.
__global__ void __launch_bounds__(T) givens_tail_kernel(const float* __restrict__ x,
                                                        float* __restrict__ y,
                                                        int row0) {
    __shared__ __align__(16) float wtQ[8];
    __shared__ float sxe[8];
    __shared__ float sx01[2];

    const int t = threadIdx.x, lid = t & 31, w = t >> 5, lo = t * E;
    const long row = row0 + blockIdx.x;
    const float* xr = x + row * NN;
    float* yr = y + row * NN;

    float cc[E], ss[E], xv[E];
#pragma unroll
    for (int m = 0; m < E; ++m) {
        cc[m] = g_c[lo + m]; ss[m] = g_s[lo + m]; xv[m] = xr[lo + m];
    }
    float W[5];
#pragma unroll
    for (int di = 0; di < 5; ++di) W[di] = g_W5[di][t];
    const float Pe = g_Pe[t], Pf = g_PfA[t];
    const float cN = g_c[NN - 1], sN = g_s[NN - 1];
    const bool warp_head = (lid == 0) && (w > 0);

    if (lid == 31) sxe[w] = xv[7];
    if (t == 0)    sx01[0] = xv[0];
    if (t == T-1)  sx01[1] = xv[7];

    float Q = 0.f;
#pragma unroll
    for (int m = E - 1; m >= 0; --m) {
        if (lo + m == NN - 1) continue;
        Q = fmaf(-ss[m], Q, cc[m] * xv[m]);
    }
#pragma unroll
    for (int di = 0, d = 1; di < 5; ++di, d <<= 1) {
        float q2 = __shfl_down_sync(0xffffffffu, Q, d);
        Q = fmaf(W[di], q2, Q);
    }
    float Qe = __shfl_down_sync(0xffffffffu, Q, 1);
    if (lid == 31) Qe = 0.f;
    if (lid == 0) wtQ[w] = Q;
    __syncthreads();

    float Qp = 0.f;
    for (int w2 = 7; w2 > w; --w2) Qp = fmaf(g_Pw[w2], Qp, wtQ[w2]);
    const float x0 = sx01[0], xn1 = sx01[1];
    const float seed = fmaf(cN, xn1, -sN * x0);
    if (t == 0) xv[0] = fmaf(sN, xn1, cN * x0);
    float prev = fmaf(Pf, seed, fmaf(Pe, Qp, Qe));

#pragma unroll
    for (int m = E - 1; m >= 0; --m) {
        if (lo + m == NN - 1) { xv[m] = 0.f; continue; }
        const float xm = xv[m];
        xv[m] = fmaf(ss[m], xm, cc[m] * prev);
        prev  = fmaf(-ss[m], prev, cc[m] * xm);
    }
    float carry = __shfl_up_sync(0xffffffffu, xv[E - 1], 1);
    if (t == 0)         carry = prev;
    else if (warp_head) carry = fmaf(g_s[lo - 1], sxe[w - 1], g_c[lo - 1] * prev);

    float4 o0, o1;
    o0.x = carry; o0.y = xv[0]; o0.z = xv[1]; o0.w = xv[2];
    o1.x = xv[3]; o1.y = xv[4]; o1.z = xv[5]; o1.w = xv[6];
    reinterpret_cast<float4*>(yr + lo)[0] = o0;
    reinterpret_cast<float4*>(yr + lo)[1] = o1;
}

extern "C" void kernel_launch(void* const* d_in, const int* in_sizes, int n_in,
                              void* d_out, int out_size) {
    const float* x   = (const float*)d_in[0];   // (B, N) fp32
    const float* ang = (const float*)d_in[1];   // (N,)  fp32
    float* y = (float*)d_out;                   // (B, N) fp32

    prep_kernel<<<1, T>>>(ang);

    const int rows = out_size / NN;             // B = 16384
    const int full = rows / R;                  // 2048 full blocks
    if (full > 0) givens_kernel<<<full, T>>>(x, y);
    const int rem = rows - full * R;
    if (rem > 0) givens_tail_kernel<<<rem, T>>>(x, y, full * R);
}